// round 7
// baseline (speedup 1.0000x reference)
#include <cuda_runtime.h>

// Fixed shapes from setup_inputs
#define LQ 512   // sequence length
#define DD 256   // per-tensor feature dim
#define FD 512   // 2*DD (MLP hidden)
#define NB 2     // batch
#define NH 8     // heads
#define DK 64    // head dim

// Scratch (no cudaMalloc allowed)
__device__ float g_A[NB * LQ * FD];   // d1 @ W1[:DD]
__device__ float g_C[NB * LQ * FD];   // d0 @ W1[DD:] + b1
__device__ float g_D[NB * LQ * LQ];   // decisions: 0 or -1e9

typedef unsigned long long u64;

// Packed f32x2 (sm_100+): 2 fp32 lanes per fma-pipe instruction.
#define FFMA2(d,a,b,c) asm("fma.rn.f32x2 %0,%1,%2,%3;" : "=l"(d) : "l"(a),"l"(b),"l"(c))
#define FADD2(d,a,b)   asm("add.rn.f32x2 %0,%1,%2;"    : "=l"(d) : "l"(a),"l"(b))

__device__ __forceinline__ float2 unpk(u64 p) {
    float lo, hi;
    asm("mov.b64 {%0,%1},%2;" : "=f"(lo), "=f"(hi) : "l"(p));
    return make_float2(lo, hi);
}
__device__ __forceinline__ u64 pk(float lo, float hi) {
    u64 d;
    asm("mov.b64 %0,{%1,%2};" : "=l"(d) : "f"(lo), "f"(hi));
    return d;
}

// ---------------------------------------------------------------------------
// Kernel 1: A = d1 @ W1_top ; C = d0 @ W1_bot + b1   (M=1024, N=512, K=256)
// Tile 64m x 64n, 128 threads, per-thread 8i x 4j (2 packed pairs), chunk 16.
// a-side: scalar LDS + register broadcast (mov.b64 {a,a}); b-side: natural
// pairs via one LDS.128. Software-pipelined global fill. Grid 8x16x2 = 256.
// ---------------------------------------------------------------------------
__global__ __launch_bounds__(128) void gemm_ac_kernel(
    const float* __restrict__ d1, const float* __restrict__ d0,
    const float* __restrict__ W1, const float* __restrict__ b1)
{
    const int z = blockIdx.z;                       // 0 -> A, 1 -> C
    const float* __restrict__ src = z ? d0 : d1;    // [1024, 256]
    const float* __restrict__ W   = W1 + (z ? DD * FD : 0);  // [256, 512]
    float* dst = z ? g_C : g_A;

    __shared__ __align__(16) float As_T[16 * 64];   // [k][m] transposed
    __shared__ __align__(16) float Bs[16 * 64];     // [k][n]

    const int m0 = blockIdx.y * 64, n0 = blockIdx.x * 64;
    const int t  = threadIdx.x;
    const int jx = t & 15, iy = t >> 4;             // iy 0..7 (8i), jx 0..15 (4j)
    const int ii = t & 63, half = t >> 6;           // A fill: 64 rows x 2 k-halves
    const int bk = t >> 3, nq = t & 7;              // B fill: 16 k-rows x 8 groups

    const float* aptr = src + (m0 + ii) * DD + half * 8;
    const float* bptr = W + bk * FD + n0 + nq * 8;

    u64 acc[8][2] = {};
    float4 a0, a1, b0, b1v;

    // prefetch chunk 0
    a0 = *(const float4*)(aptr + 0);
    a1 = *(const float4*)(aptr + 4);
    b0 = *(const float4*)(bptr + 0);
    b1v = *(const float4*)(bptr + 4);

    for (int c = 0; c < DD / 16; c++) {
        __syncthreads();
        // store staged chunk to smem (A transposed scatter)
        As_T[(half * 8 + 0) * 64 + ii] = a0.x;
        As_T[(half * 8 + 1) * 64 + ii] = a0.y;
        As_T[(half * 8 + 2) * 64 + ii] = a0.z;
        As_T[(half * 8 + 3) * 64 + ii] = a0.w;
        As_T[(half * 8 + 4) * 64 + ii] = a1.x;
        As_T[(half * 8 + 5) * 64 + ii] = a1.y;
        As_T[(half * 8 + 6) * 64 + ii] = a1.z;
        As_T[(half * 8 + 7) * 64 + ii] = a1.w;
        *(float4*)&Bs[bk * 64 + nq * 8]     = b0;
        *(float4*)&Bs[bk * 64 + nq * 8 + 4] = b1v;
        __syncthreads();

        if (c + 1 < DD / 16) {
            int k0 = (c + 1) * 16;
            a0 = *(const float4*)(aptr + k0);
            a1 = *(const float4*)(aptr + k0 + 4);
            b0 = *(const float4*)(bptr + k0 * FD);
            b1v = *(const float4*)(bptr + k0 * FD + 4);
        }

        #pragma unroll
        for (int kk = 0; kk < 16; kk++) {
            const float* ap = &As_T[kk * 64 + iy * 8];
            float4 alo = *(const float4*)ap;
            float4 ahi = *(const float4*)(ap + 4);
            ulonglong2 bp = *(const ulonglong2*)&Bs[kk * 64 + jx * 4];
            float av[8] = {alo.x, alo.y, alo.z, alo.w, ahi.x, ahi.y, ahi.z, ahi.w};
            #pragma unroll
            for (int i = 0; i < 8; i++) {
                u64 ad = pk(av[i], av[i]);
                FFMA2(acc[i][0], ad, bp.x, acc[i][0]);
                FFMA2(acc[i][1], ad, bp.y, acc[i][1]);
            }
        }
    }

    float4 bv = make_float4(0.f, 0.f, 0.f, 0.f);
    if (z) bv = *(const float4*)&b1[n0 + jx * 4];

    #pragma unroll
    for (int i = 0; i < 8; i++) {
        float2 p0 = unpk(acc[i][0]), p1 = unpk(acc[i][1]);
        float4 r = make_float4(p0.x + bv.x, p0.y + bv.y, p1.x + bv.z, p1.y + bv.w);
        *(float4*)&dst[(m0 + iy * 8 + i) * FD + n0 + jx * 4] = r;
    }
}

// ---------------------------------------------------------------------------
// Kernel 2: decisions[b,i,j] = (sum_f relu(A[b,i,f]+C[b,j,f])*w2d[f] + b2d > 0)
//           ? -1e9 : 0.   Tile 64x64, 256 threads, per-thread 4i x 4j, chunk 32
//           with chunk-local partials (bit-identical to R1's summation order).
//           Grid 8x8x2 = 128.
// ---------------------------------------------------------------------------
__global__ __launch_bounds__(256) void decisions_kernel(
    const float* __restrict__ W2, const float* __restrict__ b2)
{
    const int b  = blockIdx.z;
    const int i0 = blockIdx.y * 64;
    const int j0 = blockIdx.x * 64;
    const float* __restrict__ Ab = g_A + b * LQ * FD;
    const float* __restrict__ Cb = g_C + b * LQ * FD;

    __shared__ __align__(16) float As_T[32 * 64];   // [f][i]
    __shared__ __align__(16) float Cs[32 * 64];     // [f][j]
    __shared__ __align__(16) float2 ws2[FD];        // {w,w} pairs

    const int t  = threadIdx.x;
    const int jx = t & 15, iy = t >> 4;             // iy 0..15 (4i), jx 0..15 (4j)
    const int ii = t & 63, half = t >> 6;           // fills: 64 rows x 4 f-eighths

    for (int f = t; f < FD; f += 256) {
        float w = W2[2 * f + 1] - W2[2 * f];
        ws2[f] = make_float2(w, w);
    }

    const float* aptr = Ab + (i0 + ii) * FD + half * 8;
    const float* cptr = Cb + (j0 + ii) * FD + half * 8;

    u64 acc[4][2] = {};
    float4 aa0, aa1, cc0, cc1;

    aa0 = *(const float4*)(aptr + 0);
    aa1 = *(const float4*)(aptr + 4);
    cc0 = *(const float4*)(cptr + 0);
    cc1 = *(const float4*)(cptr + 4);

    for (int c = 0; c < FD / 32; c++) {
        const int f0 = c * 32;
        __syncthreads();
        As_T[(half * 8 + 0) * 64 + ii] = aa0.x;
        As_T[(half * 8 + 1) * 64 + ii] = aa0.y;
        As_T[(half * 8 + 2) * 64 + ii] = aa0.z;
        As_T[(half * 8 + 3) * 64 + ii] = aa0.w;
        As_T[(half * 8 + 4) * 64 + ii] = aa1.x;
        As_T[(half * 8 + 5) * 64 + ii] = aa1.y;
        As_T[(half * 8 + 6) * 64 + ii] = aa1.z;
        As_T[(half * 8 + 7) * 64 + ii] = aa1.w;
        Cs[(half * 8 + 0) * 64 + ii] = cc0.x;
        Cs[(half * 8 + 1) * 64 + ii] = cc0.y;
        Cs[(half * 8 + 2) * 64 + ii] = cc0.z;
        Cs[(half * 8 + 3) * 64 + ii] = cc0.w;
        Cs[(half * 8 + 4) * 64 + ii] = cc1.x;
        Cs[(half * 8 + 5) * 64 + ii] = cc1.y;
        Cs[(half * 8 + 6) * 64 + ii] = cc1.z;
        Cs[(half * 8 + 7) * 64 + ii] = cc1.w;
        __syncthreads();

        if (c + 1 < FD / 32) {
            int fn = (c + 1) * 32;
            aa0 = *(const float4*)(aptr + fn);
            aa1 = *(const float4*)(aptr + fn + 4);
            cc0 = *(const float4*)(cptr + fn);
            cc1 = *(const float4*)(cptr + fn + 4);
        }

        u64 accC[4][2] = {};
        #pragma unroll
        for (int kk = 0; kk < 32; kk++) {
            float4 a4 = *(const float4*)&As_T[kk * 64 + iy * 4];
            ulonglong2 cp = *(const ulonglong2*)&Cs[kk * 64 + jx * 4];
            u64 wd = *(const u64*)&ws2[f0 + kk];
            float av[4] = {a4.x, a4.y, a4.z, a4.w};
            #pragma unroll
            for (int i = 0; i < 4; i++) {
                u64 ad = pk(av[i], av[i]);
                u64 s;  float2 h;  u64 r;
                FADD2(s, ad, cp.x); h = unpk(s);
                r = pk(fmaxf(h.x, 0.f), fmaxf(h.y, 0.f));
                FFMA2(accC[i][0], r, wd, accC[i][0]);
                FADD2(s, ad, cp.y); h = unpk(s);
                r = pk(fmaxf(h.x, 0.f), fmaxf(h.y, 0.f));
                FFMA2(accC[i][1], r, wd, accC[i][1]);
            }
        }
        #pragma unroll
        for (int i = 0; i < 4; i++) {
            FADD2(acc[i][0], acc[i][0], accC[i][0]);
            FADD2(acc[i][1], acc[i][1], accC[i][1]);
        }
    }

    const float b2d = b2[1] - b2[0];
    float* Db = g_D + b * LQ * LQ;
    #pragma unroll
    for (int i = 0; i < 4; i++) {
        float2 p0 = unpk(acc[i][0]), p1 = unpk(acc[i][1]);
        float4 r = make_float4(
            (p0.x + b2d > 0.f) ? -1e9f : 0.f, (p0.y + b2d > 0.f) ? -1e9f : 0.f,
            (p1.x + b2d > 0.f) ? -1e9f : 0.f, (p1.y + b2d > 0.f) ? -1e9f : 0.f);
        *(float4*)&Db[(i0 + iy * 4 + i) * LQ + j0 + jx * 4] = r;
    }
}

// ---------------------------------------------------------------------------
// Kernel 3: out[b,n,i,j] = dot(q[b,n,i,:], k[b,n,j,:]) * 0.125 + D[b,i,j]
// Tile 128i x 64j, 128 threads, per-thread 8i x 8j, chunk 16 over d (4 chunks).
// Grid 8x4x16 = 512.
// ---------------------------------------------------------------------------
__global__ __launch_bounds__(128) void attn_kernel(
    const float* __restrict__ q, const float* __restrict__ k,
    float* __restrict__ out)
{
    const int bn = blockIdx.z;          // b*NH + n
    const int b  = bn >> 3;
    const int i0 = blockIdx.y * 128;
    const int j0 = blockIdx.x * 64;
    const float* __restrict__ Q = q + bn * LQ * DK;
    const float* __restrict__ K = k + bn * LQ * DK;

    __shared__ __align__(16) float Qs_T[16 * 128];  // [d][i]
    __shared__ __align__(16) float Ks_T[16 * 64];   // [d][j]

    const int t  = threadIdx.x;
    const int jx = t & 7, iy = t >> 3;              // iy 0..15 (8i), jx 0..7 (8j)
    const int jj = t & 63, half = t >> 6;           // K fill: 64 rows x 2 d-halves

    const float* qptr = Q + (i0 + t) * DK;          // one i-row per thread
    const float* kptr = K + (j0 + jj) * DK + half * 8;

    u64 acc[8][4] = {};
    float4 q0, q1, q2, q3, k0v, k1v;

    q0 = *(const float4*)(qptr + 0);
    q1 = *(const float4*)(qptr + 4);
    q2 = *(const float4*)(qptr + 8);
    q3 = *(const float4*)(qptr + 12);
    k0v = *(const float4*)(kptr + 0);
    k1v = *(const float4*)(kptr + 4);

    for (int c = 0; c < DK / 16; c++) {
        __syncthreads();
        Qs_T[ 0 * 128 + t] = q0.x;  Qs_T[ 1 * 128 + t] = q0.y;
        Qs_T[ 2 * 128 + t] = q0.z;  Qs_T[ 3 * 128 + t] = q0.w;
        Qs_T[ 4 * 128 + t] = q1.x;  Qs_T[ 5 * 128 + t] = q1.y;
        Qs_T[ 6 * 128 + t] = q1.z;  Qs_T[ 7 * 128 + t] = q1.w;
        Qs_T[ 8 * 128 + t] = q2.x;  Qs_T[ 9 * 128 + t] = q2.y;
        Qs_T[10 * 128 + t] = q2.z;  Qs_T[11 * 128 + t] = q2.w;
        Qs_T[12 * 128 + t] = q3.x;  Qs_T[13 * 128 + t] = q3.y;
        Qs_T[14 * 128 + t] = q3.z;  Qs_T[15 * 128 + t] = q3.w;
        Ks_T[(half * 8 + 0) * 64 + jj] = k0v.x;
        Ks_T[(half * 8 + 1) * 64 + jj] = k0v.y;
        Ks_T[(half * 8 + 2) * 64 + jj] = k0v.z;
        Ks_T[(half * 8 + 3) * 64 + jj] = k0v.w;
        Ks_T[(half * 8 + 4) * 64 + jj] = k1v.x;
        Ks_T[(half * 8 + 5) * 64 + jj] = k1v.y;
        Ks_T[(half * 8 + 6) * 64 + jj] = k1v.z;
        Ks_T[(half * 8 + 7) * 64 + jj] = k1v.w;
        __syncthreads();

        if (c + 1 < DK / 16) {
            int d0 = (c + 1) * 16;
            q0 = *(const float4*)(qptr + d0);
            q1 = *(const float4*)(qptr + d0 + 4);
            q2 = *(const float4*)(qptr + d0 + 8);
            q3 = *(const float4*)(qptr + d0 + 12);
            k0v = *(const float4*)(kptr + d0);
            k1v = *(const float4*)(kptr + d0 + 4);
        }

        #pragma unroll
        for (int kk = 0; kk < 16; kk++) {
            const float* ap = &Qs_T[kk * 128 + iy * 8];
            float4 alo = *(const float4*)ap;
            float4 ahi = *(const float4*)(ap + 4);
            ulonglong2 b01 = *(const ulonglong2*)&Ks_T[kk * 64 + jx * 8];
            ulonglong2 b23 = *(const ulonglong2*)&Ks_T[kk * 64 + jx * 8 + 4];
            float av[8] = {alo.x, alo.y, alo.z, alo.w, ahi.x, ahi.y, ahi.z, ahi.w};
            #pragma unroll
            for (int i = 0; i < 8; i++) {
                u64 ad = pk(av[i], av[i]);
                FFMA2(acc[i][0], ad, b01.x, acc[i][0]);
                FFMA2(acc[i][1], ad, b01.y, acc[i][1]);
                FFMA2(acc[i][2], ad, b23.x, acc[i][2]);
                FFMA2(acc[i][3], ad, b23.y, acc[i][3]);
            }
        }
    }

    const float* Db = g_D + b * LQ * LQ;
    float* O = out + bn * LQ * LQ;
    #pragma unroll
    for (int i = 0; i < 8; i++) {
        int row = i0 + iy * 8 + i;
        float4 dv0 = *(const float4*)&Db[row * LQ + j0 + jx * 8];
        float4 dv1 = *(const float4*)&Db[row * LQ + j0 + jx * 8 + 4];
        float2 p0 = unpk(acc[i][0]), p1 = unpk(acc[i][1]);
        float2 p2 = unpk(acc[i][2]), p3 = unpk(acc[i][3]);
        float4 r0 = make_float4(p0.x * 0.125f + dv0.x, p0.y * 0.125f + dv0.y,
                                p1.x * 0.125f + dv0.z, p1.y * 0.125f + dv0.w);
        float4 r1 = make_float4(p2.x * 0.125f + dv1.x, p2.y * 0.125f + dv1.y,
                                p3.x * 0.125f + dv1.z, p3.y * 0.125f + dv1.w);
        *(float4*)&O[row * LQ + j0 + jx * 8]     = r0;
        *(float4*)&O[row * LQ + j0 + jx * 8 + 4] = r1;
    }
}

// ---------------------------------------------------------------------------
// Inputs (metadata order): q, k, d0, d1, W1, b1, W2, b2
// ---------------------------------------------------------------------------
extern "C" void kernel_launch(void* const* d_in, const int* in_sizes, int n_in,
                              void* d_out, int out_size)
{
    const float* q  = (const float*)d_in[0];   // [2,8,512,64]
    const float* k  = (const float*)d_in[1];   // [2,8,512,64]
    const float* d0 = (const float*)d_in[2];   // [2,512,256]
    const float* d1 = (const float*)d_in[3];   // [2,512,256]
    const float* W1 = (const float*)d_in[4];   // [512,512]
    const float* b1 = (const float*)d_in[5];   // [512]
    const float* W2 = (const float*)d_in[6];   // [512,2]
    const float* b2 = (const float*)d_in[7];   // [2]
    float* out = (float*)d_out;                // [2,8,512,512]

    (void)in_sizes; (void)n_in; (void)out_size;

    gemm_ac_kernel  <<<dim3(FD / 64, (NB * LQ) / 64, 2),    128>>>(d1, d0, W1, b1);
    decisions_kernel<<<dim3(LQ / 64, LQ / 64, NB),          256>>>(W2, b2);
    attn_kernel     <<<dim3(LQ / 64, LQ / 128, NB * NH),    128>>>(q, k, out);
}

// round 8
// speedup vs baseline: 3.7833x; 3.7833x over previous
#include <cuda_runtime.h>

// Fixed shapes from setup_inputs
#define LQ 512   // sequence length
#define DD 256   // per-tensor feature dim
#define FD 512   // 2*DD (MLP hidden)
#define NB 2     // batch
#define NH 8     // heads
#define DK 64    // head dim

// Scratch (no cudaMalloc allowed)
__device__ float g_A[NB * LQ * FD];   // d1 @ W1[:DD]
__device__ float g_C[NB * LQ * FD];   // d0 @ W1[DD:] + b1
__device__ float g_D[NB * LQ * LQ];   // decisions: 0 or -1e9

typedef unsigned long long u64;

// Packed f32x2 (sm_100+). Used ONLY in decisions (no packed relu exists;
// relu is done via the exact identity relu(x)*w == (x+|x|)*(w/2), where
// |x| on a packed pair is a single and.b64 on the alu pipe).
#define FFMA2(d,a,b,c) asm("fma.rn.f32x2 %0,%1,%2,%3;" : "=l"(d) : "l"(a),"l"(b),"l"(c))
#define FADD2(d,a,b)   asm("add.rn.f32x2 %0,%1,%2;"    : "=l"(d) : "l"(a),"l"(b))

__device__ __forceinline__ float2 unpk(u64 p) {
    float lo, hi;
    asm("mov.b64 {%0,%1},%2;" : "=f"(lo), "=f"(hi) : "l"(p));
    return make_float2(lo, hi);
}
__device__ __forceinline__ u64 pk(float lo, float hi) {
    u64 d;
    asm("mov.b64 %0,{%1,%2};" : "=l"(d) : "f"(lo), "f"(hi));
    return d;
}

// ---------------------------------------------------------------------------
// Kernel 1: A = d1 @ W1_top ; C = d0 @ W1_bot + b1   (M=1024, N=512, K=256)
// Scalar microkernel: 64m x 64n tile, 128 threads, per-thread 8i x 4j,
// K-chunk 16. Inner loop: 3x LDS.128 + 32 FFMA (fma-bound).
// Grid 8 x 16 x 2 = 256 blocks.
// ---------------------------------------------------------------------------
__global__ __launch_bounds__(128) void gemm_ac_kernel(
    const float* __restrict__ d1, const float* __restrict__ d0,
    const float* __restrict__ W1, const float* __restrict__ b1)
{
    const int z = blockIdx.z;                       // 0 -> A, 1 -> C
    const float* __restrict__ src = z ? d0 : d1;    // [1024, 256]
    const float* __restrict__ W   = W1 + (z ? DD * FD : 0);  // [256, 512]
    float* dst = z ? g_C : g_A;

    __shared__ __align__(16) float As_T[16 * 64];   // [k][m] transposed
    __shared__ __align__(16) float Bs[16 * 64];     // [k][n]

    const int m0 = blockIdx.y * 64, n0 = blockIdx.x * 64;
    const int t  = threadIdx.x;
    const int jx = t & 15, iy = t >> 4;             // iy 0..7 (8i), jx 0..15 (4j)
    const int ii = t & 63, hf = t >> 6;             // A fill: row ii, k-half hf
    const int bk = t >> 3, nq = t & 7;              // B fill: k-row bk, 8n group

    float acc[8][4] = {};

    for (int k0 = 0; k0 < DD; k0 += 16) {
        __syncthreads();
        {
            float4 a0 = *(const float4*)&src[(m0 + ii) * DD + k0 + hf * 8];
            float4 a1 = *(const float4*)&src[(m0 + ii) * DD + k0 + hf * 8 + 4];
            As_T[(hf * 8 + 0) * 64 + ii] = a0.x;
            As_T[(hf * 8 + 1) * 64 + ii] = a0.y;
            As_T[(hf * 8 + 2) * 64 + ii] = a0.z;
            As_T[(hf * 8 + 3) * 64 + ii] = a0.w;
            As_T[(hf * 8 + 4) * 64 + ii] = a1.x;
            As_T[(hf * 8 + 5) * 64 + ii] = a1.y;
            As_T[(hf * 8 + 6) * 64 + ii] = a1.z;
            As_T[(hf * 8 + 7) * 64 + ii] = a1.w;
            *(float4*)&Bs[bk * 64 + nq * 8] =
                *(const float4*)&W[(k0 + bk) * FD + n0 + nq * 8];
            *(float4*)&Bs[bk * 64 + nq * 8 + 4] =
                *(const float4*)&W[(k0 + bk) * FD + n0 + nq * 8 + 4];
        }
        __syncthreads();

        #pragma unroll
        for (int kk = 0; kk < 16; kk++) {
            float4 alo = *(const float4*)&As_T[kk * 64 + iy * 8];
            float4 ahi = *(const float4*)&As_T[kk * 64 + iy * 8 + 4];
            float4 b4  = *(const float4*)&Bs[kk * 64 + jx * 4];
            float a[8] = {alo.x, alo.y, alo.z, alo.w, ahi.x, ahi.y, ahi.z, ahi.w};
            #pragma unroll
            for (int i = 0; i < 8; i++) {
                acc[i][0] = fmaf(a[i], b4.x, acc[i][0]);
                acc[i][1] = fmaf(a[i], b4.y, acc[i][1]);
                acc[i][2] = fmaf(a[i], b4.z, acc[i][2]);
                acc[i][3] = fmaf(a[i], b4.w, acc[i][3]);
            }
        }
    }

    float4 bv = make_float4(0.f, 0.f, 0.f, 0.f);
    if (z) bv = *(const float4*)&b1[n0 + jx * 4];

    #pragma unroll
    for (int i = 0; i < 8; i++) {
        float4 r = make_float4(acc[i][0] + bv.x, acc[i][1] + bv.y,
                               acc[i][2] + bv.z, acc[i][3] + bv.w);
        *(float4*)&dst[(m0 + iy * 8 + i) * FD + n0 + jx * 4] = r;
    }
}

// ---------------------------------------------------------------------------
// Kernel 2: decisions[b,i,j] = (sum_f relu(A[b,i,f]+C[b,j,f])*w2d[f] + b2d > 0)
//           ? -1e9 : 0
// Packed-j: 64i x 32j tile, 256 threads, per-thread 4i x 2j (one pair).
// relu via exact identity: relu(s)*w = (s+|s|)*(w/2); |s| = and.b64.
// Chunk-32 partials reproduce R1's exact per-lane summation order.
// Grid 16 x 8 x 2 = 256 blocks.
// ---------------------------------------------------------------------------
__global__ __launch_bounds__(256) void decisions_kernel(
    const float* __restrict__ W2, const float* __restrict__ b2)
{
    const int b  = blockIdx.z;
    const int i0 = blockIdx.y * 64;
    const int j0 = blockIdx.x * 32;
    const float* __restrict__ Ab = g_A + b * LQ * FD;
    const float* __restrict__ Cb = g_C + b * LQ * FD;

    __shared__ __align__(16) float As_T[32 * 64];   // [f][i]
    __shared__ __align__(16) float Cs[32 * 32];     // [f][j]
    __shared__ __align__(16) float2 ws2[FD];        // {w/2, w/2}

    const int t  = threadIdx.x;
    const int jx = t & 15, iy = t >> 4;             // iy 0..15 (4i), jx 0..15 (2j)
    const int ii = t & 63, fq  = t >> 6;            // A fill: row ii, f-eighth fq
    const int jj = t & 31, fq2 = t >> 5;            // C fill: row jj, f-quad fq2

    for (int f = t; f < FD; f += 256) {
        float w = 0.5f * (W2[2 * f + 1] - W2[2 * f]);
        ws2[f] = make_float2(w, w);
    }

    u64 acc[4] = {};

    for (int f0 = 0; f0 < FD; f0 += 32) {
        __syncthreads();
        {
            float4 a0 = *(const float4*)&Ab[(i0 + ii) * FD + f0 + fq * 8];
            float4 a1 = *(const float4*)&Ab[(i0 + ii) * FD + f0 + fq * 8 + 4];
            As_T[(fq * 8 + 0) * 64 + ii] = a0.x;
            As_T[(fq * 8 + 1) * 64 + ii] = a0.y;
            As_T[(fq * 8 + 2) * 64 + ii] = a0.z;
            As_T[(fq * 8 + 3) * 64 + ii] = a0.w;
            As_T[(fq * 8 + 4) * 64 + ii] = a1.x;
            As_T[(fq * 8 + 5) * 64 + ii] = a1.y;
            As_T[(fq * 8 + 6) * 64 + ii] = a1.z;
            As_T[(fq * 8 + 7) * 64 + ii] = a1.w;
            float4 c0 = *(const float4*)&Cb[(j0 + jj) * FD + f0 + fq2 * 4];
            Cs[(fq2 * 4 + 0) * 32 + jj] = c0.x;
            Cs[(fq2 * 4 + 1) * 32 + jj] = c0.y;
            Cs[(fq2 * 4 + 2) * 32 + jj] = c0.z;
            Cs[(fq2 * 4 + 3) * 32 + jj] = c0.w;
        }
        __syncthreads();

        u64 accC[4] = {};
        #pragma unroll
        for (int kk = 0; kk < 32; kk++) {
            float4 a4 = *(const float4*)&As_T[kk * 64 + iy * 4];
            u64 cd = *(const u64*)&Cs[kk * 32 + jx * 2];
            u64 wd = *(const u64*)&ws2[f0 + kk];
            float av[4] = {a4.x, a4.y, a4.z, a4.w};
            #pragma unroll
            for (int i = 0; i < 4; i++) {
                u64 ad = pk(av[i], av[i]);
                u64 s, s2;
                FADD2(s, ad, cd);                       // s = a + c (packed)
                u64 sa = s & 0x7FFFFFFF7FFFFFFFULL;     // |s| per half (alu)
                FADD2(s2, s, sa);                       // = 2*relu(s) exactly
                FFMA2(accC[i], s2, wd, accC[i]);        // * (w/2): exact product
            }
        }
        #pragma unroll
        for (int i = 0; i < 4; i++)
            FADD2(acc[i], acc[i], accC[i]);
    }

    const float b2d = b2[1] - b2[0];
    float* Db = g_D + b * LQ * LQ;
    #pragma unroll
    for (int i = 0; i < 4; i++) {
        float2 p = unpk(acc[i]);
        float2 r = make_float2((p.x + b2d > 0.f) ? -1e9f : 0.f,
                               (p.y + b2d > 0.f) ? -1e9f : 0.f);
        *(float2*)&Db[(i0 + iy * 4 + i) * LQ + j0 + jx * 2] = r;
    }
}

// ---------------------------------------------------------------------------
// Kernel 3: out[b,n,i,j] = dot(q[b,n,i,:], k[b,n,j,:]) * 0.125 + D[b,i,j]
// Scalar microkernel: 64i x 64j tile, 128 threads, per-thread 8i x 4j,
// full K=64 staged once in smem. Grid 8 x 8 x 16 = 1024 blocks.
// ---------------------------------------------------------------------------
__global__ __launch_bounds__(128) void attn_kernel(
    const float* __restrict__ q, const float* __restrict__ k,
    float* __restrict__ out)
{
    const int bn = blockIdx.z;          // b*NH + n
    const int b  = bn >> 3;
    const int i0 = blockIdx.y * 64;
    const int j0 = blockIdx.x * 64;
    const float* __restrict__ Q = q + bn * LQ * DK;
    const float* __restrict__ K = k + bn * LQ * DK;

    __shared__ __align__(16) float Qs_T[64 * 64];   // [d][i]
    __shared__ __align__(16) float Ks_T[64 * 64];   // [d][j]

    const int t  = threadIdx.x;
    const int jx = t & 15, iy = t >> 4;             // iy 0..7 (8i), jx 0..15 (4j)
    const int ii = t & 63, hf = t >> 6;             // fills: row ii, d-half hf

    // Stage Q (transposed) and K (transposed) tiles: 32 d-values per thread.
    #pragma unroll
    for (int r = 0; r < 8; r++) {
        int d = hf * 32 + r * 4;
        float4 v = *(const float4*)&Q[(i0 + ii) * DK + d];
        Qs_T[(d + 0) * 64 + ii] = v.x;
        Qs_T[(d + 1) * 64 + ii] = v.y;
        Qs_T[(d + 2) * 64 + ii] = v.z;
        Qs_T[(d + 3) * 64 + ii] = v.w;
        float4 u = *(const float4*)&K[(j0 + ii) * DK + d];
        Ks_T[(d + 0) * 64 + ii] = u.x;
        Ks_T[(d + 1) * 64 + ii] = u.y;
        Ks_T[(d + 2) * 64 + ii] = u.z;
        Ks_T[(d + 3) * 64 + ii] = u.w;
    }
    __syncthreads();

    float acc[8][4] = {};
    #pragma unroll 16
    for (int dd = 0; dd < DK; dd++) {
        float4 alo = *(const float4*)&Qs_T[dd * 64 + iy * 8];
        float4 ahi = *(const float4*)&Qs_T[dd * 64 + iy * 8 + 4];
        float4 b4  = *(const float4*)&Ks_T[dd * 64 + jx * 4];
        float a[8] = {alo.x, alo.y, alo.z, alo.w, ahi.x, ahi.y, ahi.z, ahi.w};
        #pragma unroll
        for (int i = 0; i < 8; i++) {
            acc[i][0] = fmaf(a[i], b4.x, acc[i][0]);
            acc[i][1] = fmaf(a[i], b4.y, acc[i][1]);
            acc[i][2] = fmaf(a[i], b4.z, acc[i][2]);
            acc[i][3] = fmaf(a[i], b4.w, acc[i][3]);
        }
    }

    const float* Db = g_D + b * LQ * LQ;
    float* O = out + bn * LQ * LQ;
    #pragma unroll
    for (int i = 0; i < 8; i++) {
        int row = i0 + iy * 8 + i;
        float4 dv = *(const float4*)&Db[row * LQ + j0 + jx * 4];
        float4 r = make_float4(acc[i][0] * 0.125f + dv.x,
                               acc[i][1] * 0.125f + dv.y,
                               acc[i][2] * 0.125f + dv.z,
                               acc[i][3] * 0.125f + dv.w);
        *(float4*)&O[row * LQ + j0 + jx * 4] = r;
    }
}

// ---------------------------------------------------------------------------
// Inputs (metadata order): q, k, d0, d1, W1, b1, W2, b2
// ---------------------------------------------------------------------------
extern "C" void kernel_launch(void* const* d_in, const int* in_sizes, int n_in,
                              void* d_out, int out_size)
{
    const float* q  = (const float*)d_in[0];   // [2,8,512,64]
    const float* k  = (const float*)d_in[1];   // [2,8,512,64]
    const float* d0 = (const float*)d_in[2];   // [2,512,256]
    const float* d1 = (const float*)d_in[3];   // [2,512,256]
    const float* W1 = (const float*)d_in[4];   // [512,512]
    const float* b1 = (const float*)d_in[5];   // [512]
    const float* W2 = (const float*)d_in[6];   // [512,2]
    const float* b2 = (const float*)d_in[7];   // [2]
    float* out = (float*)d_out;                // [2,8,512,512]

    (void)in_sizes; (void)n_in; (void)out_size;

    gemm_ac_kernel  <<<dim3(FD / 64, (NB * LQ) / 64, 2),   128>>>(d1, d0, W1, b1);
    decisions_kernel<<<dim3(LQ / 32, LQ / 64, NB),         256>>>(W2, b2);
    attn_kernel     <<<dim3(LQ / 64, LQ / 64, NB * NH),    128>>>(q, k, out);
}